// round 8
// baseline (speedup 1.0000x reference)
#include <cuda_runtime.h>
#include <cuda_bf16.h>
#include <math.h>
#include <stdint.h>

#define BATCH 128
#define NPTS  1024
#define DIM   128
#define UMAX  0xFFFFFFFFu

// Scratch (device globals: allocation-free).
// g_D holds PACKED keys: high 22 bits = round-to-nearest of dist^2 float bits,
// low 10 bits = column index. Monotone in dist^2; ties -> lower index (matches
// jnp.argmin).
__device__ uint32_t       g_D[(size_t)BATCH * NPTS * NPTS];   // 512 MB
__device__ __nv_bfloat16  g_Xb[(size_t)BATCH * NPTS * DIM];   // 32 MB
__device__ float          g_norm[BATCH * NPTS];
__device__ float          g_partial[BATCH];

// ---------------------------------------------------------------------------
// Kernel 1: fused row norms (fp32 exact) + bf16 conversion. One warp per point.
// ---------------------------------------------------------------------------
__global__ void prep_kernel(const float* __restrict__ X) {
    int warp = (blockIdx.x * blockDim.x + threadIdx.x) >> 5;
    int lane = threadIdx.x & 31;
    if (warp >= BATCH * NPTS) return;
    const float4* row = (const float4*)(X + (size_t)warp * DIM);
    float4 v = row[lane];
    __nv_bfloat162* dst = (__nv_bfloat162*)(g_Xb + (size_t)warp * DIM) + lane * 2;
    dst[0] = __floats2bfloat162_rn(v.x, v.y);
    dst[1] = __floats2bfloat162_rn(v.z, v.w);
    float s = v.x * v.x + v.y * v.y + v.z * v.z + v.w * v.w;
    #pragma unroll
    for (int o = 16; o; o >>= 1) s += __shfl_down_sync(0xffffffffu, s, o);
    if (lane == 0) g_norm[warp] = s;
}

// ---------------------------------------------------------------------------
// Kernel 2: batched Gram via bf16 mma.sync; epilogue packs dist^2 keys.
// launch_bounds (256, 2): 2 CTAs/SM (R7 accidentally capped it at 1, leaving
// the LDS+HMMA dependency chains exposed with only 8 warps/SM).
// ---------------------------------------------------------------------------
#define KCH   64
#define LDR   72   // padded smem row length in bf16 (conflict-free)

__device__ __forceinline__ void mma16816(float* c, const uint32_t* a,
                                         uint32_t b0, uint32_t b1) {
    asm volatile(
        "mma.sync.aligned.m16n8k16.row.col.f32.bf16.bf16.f32 "
        "{%0,%1,%2,%3}, {%4,%5,%6,%7}, {%8,%9}, {%0,%1,%2,%3};\n"
        : "+f"(c[0]), "+f"(c[1]), "+f"(c[2]), "+f"(c[3])
        : "r"(a[0]), "r"(a[1]), "r"(a[2]), "r"(a[3]), "r"(b0), "r"(b1));
}

__device__ __forceinline__ uint32_t pack_key(float d2, int col) {
    return ((__float_as_uint(d2) + 0x200u) & 0xFFFFFC00u) | (uint32_t)col;
}

__global__ __launch_bounds__(256, 2)
void dist_kernel() {
    __shared__ __align__(16) __nv_bfloat16 As[128 * LDR];
    __shared__ __align__(16) __nv_bfloat16 Bs[128 * LDR];

    const int b  = blockIdx.z;
    const int I  = blockIdx.y * 128;
    const int J  = blockIdx.x * 128;
    const int tid  = threadIdx.x;
    const int lane = tid & 31;
    const int wid  = tid >> 5;
    const int wm   = wid & 3;
    const int wn   = wid >> 2;

    const __nv_bfloat16* Xb = g_Xb + (size_t)b * NPTS * DIM;

    float acc[2][8][4];
    #pragma unroll
    for (int m = 0; m < 2; ++m)
        #pragma unroll
        for (int n = 0; n < 8; ++n)
            #pragma unroll
            for (int q = 0; q < 4; ++q) acc[m][n][q] = 0.f;

    const uint32_t* As32 = (const uint32_t*)As;
    const uint32_t* Bs32 = (const uint32_t*)Bs;

    for (int k0 = 0; k0 < DIM; k0 += KCH) {
        __syncthreads();
        #pragma unroll
        for (int i = 0; i < 4; ++i) {
            int e  = tid + 256 * i;
            int r  = e >> 3;
            int c8 = e & 7;
            uint4 va = *(const uint4*)(Xb + (size_t)(I + r) * DIM + k0 + c8 * 8);
            uint4 vb = *(const uint4*)(Xb + (size_t)(J + r) * DIM + k0 + c8 * 8);
            *(uint4*)(As + r * LDR + c8 * 8) = va;
            *(uint4*)(Bs + r * LDR + c8 * 8) = vb;
        }
        __syncthreads();

        #pragma unroll
        for (int ks = 0; ks < KCH / 16; ++ks) {
            const int c = ks * 16 + (lane & 3) * 2;
            uint32_t a[2][4];
            #pragma unroll
            for (int mt = 0; mt < 2; ++mt) {
                int r0 = wm * 32 + mt * 16 + (lane >> 2);
                a[mt][0] = As32[(r0 * LDR + c) >> 1];
                a[mt][1] = As32[((r0 + 8) * LDR + c) >> 1];
                a[mt][2] = As32[(r0 * LDR + c + 8) >> 1];
                a[mt][3] = As32[((r0 + 8) * LDR + c + 8) >> 1];
            }
            #pragma unroll
            for (int nt = 0; nt < 8; ++nt) {
                int jr = wn * 64 + nt * 8 + (lane >> 2);
                uint32_t b0 = Bs32[(jr * LDR + c) >> 1];
                uint32_t b1 = Bs32[(jr * LDR + c + 8) >> 1];
                mma16816(acc[0][nt], a[0], b0, b1);
                mma16816(acc[1][nt], a[1], b0, b1);
            }
        }
    }

    uint32_t* Db = g_D + ((size_t)b << 20);
    const float* nb = g_norm + b * NPTS;
    #pragma unroll
    for (int mt = 0; mt < 2; ++mt) {
        int r0 = I + wm * 32 + mt * 16 + (lane >> 2);
        float ni0 = nb[r0], ni1 = nb[r0 + 8];
        #pragma unroll
        for (int nt = 0; nt < 8; ++nt) {
            int col = J + wn * 64 + nt * 8 + (lane & 3) * 2;
            float nj0 = nb[col], nj1 = nb[col + 1];
            uint2 v0, v1;
            v0.x = pack_key(fmaxf(ni0 + nj0 - 2.f * acc[mt][nt][0], 0.f), col);
            v0.y = pack_key(fmaxf(ni0 + nj1 - 2.f * acc[mt][nt][1], 0.f), col + 1);
            v1.x = pack_key(fmaxf(ni1 + nj0 - 2.f * acc[mt][nt][2], 0.f), col);
            v1.y = pack_key(fmaxf(ni1 + nj1 - 2.f * acc[mt][nt][3], 0.f), col + 1);
            *(uint2*)(Db + (size_t)r0 * NPTS + col)       = v0;
            *(uint2*)(Db + (size_t)(r0 + 8) * NPTS + col) = v1;
        }
    }
}

// ---------------------------------------------------------------------------
// Kernel 3: Prim's MST. 256 threads/CTA, 4 consecutive points/thread.
// ONE barrier per iteration: per-warp (min, second) pairs go into a
// parity-double-buffered smem array; after the barrier EVERY thread loads all
// 8 pairs (64B broadcast) and combines gbest/gsec redundantly — removing the
// warp-0 funnel + second barrier (~200 cyc) from the serial chain.
// Sticky visited stays explicit (R3/R5 lesson):
//   m_e = (m_e==UMAX || idx_e==j) ? UMAX : min(m_e, row_e).
// Top-1 speculation on gsec (provably the only predictable next-winner):
// its row is prefetched so a hit hides the ~600-cycle DRAM row fetch.
// ---------------------------------------------------------------------------
__device__ __forceinline__ uint32_t upd(uint32_t m, uint32_t r, int idx, int j) {
    uint32_t nx = min(m, r);
    return (m == UMAX || idx == j) ? UMAX : nx;
}

__global__ __launch_bounds__(256, 1)
void prim_kernel() {
    const int b    = blockIdx.x;
    const int tid  = threadIdx.x;
    const int lane = tid & 31;
    const int wid  = tid >> 5;
    const int p0   = tid * 4;

    const uint32_t* Db = g_D + ((size_t)b << 20);

    // init: mind = row 0 keys; point 0 marked visited
    uint4 m = ((const uint4*)Db)[tid];
    if (tid == 0) m.x = UMAX;

    __shared__ __align__(16) uint2 s_warp[2][8];   // [parity][warp] (min, second)

    float total = 0.f;
    int spec_idx = -1;
    uint4 SPEC;

    for (int it = 0; it < NPTS - 1; ++it) {
        const int par = it & 1;
        // ---- per-thread min of 4, then warp (min, second) via 2 REDUX ----
        uint32_t km = min(min(m.x, m.y), min(m.z, m.w));
        uint32_t wbest = __reduce_min_sync(0xffffffffu, km);
        uint32_t km2   = (km == wbest) ? UMAX : km;
        uint32_t wsec  = __reduce_min_sync(0xffffffffu, km2);
        if (lane == 0) s_warp[par][wid] = make_uint2(wbest, wsec);
        __syncthreads();   // the ONLY barrier this iteration

        // ---- every thread combines the 8 pairs locally (broadcast LDS) ----
        uint4 q0 = *(const uint4*)&s_warp[par][0];   // (b0,s0,b1,s1)
        uint4 q1 = *(const uint4*)&s_warp[par][2];
        uint4 q2 = *(const uint4*)&s_warp[par][4];
        uint4 q3 = *(const uint4*)&s_warp[par][6];
        uint32_t gbest = min(min(min(q0.x, q0.z), min(q1.x, q1.z)),
                             min(min(q2.x, q2.z), min(q3.x, q3.z)));
        // candidate for second: winner warp contributes its second, others their min
        uint32_t c0 = (q0.x == gbest) ? q0.y : q0.x;
        uint32_t c1 = (q0.z == gbest) ? q0.w : q0.z;
        uint32_t c2 = (q1.x == gbest) ? q1.y : q1.x;
        uint32_t c3 = (q1.z == gbest) ? q1.w : q1.z;
        uint32_t c4 = (q2.x == gbest) ? q2.y : q2.x;
        uint32_t c5 = (q2.z == gbest) ? q2.w : q2.z;
        uint32_t c6 = (q3.x == gbest) ? q3.y : q3.x;
        uint32_t c7 = (q3.z == gbest) ? q3.w : q3.z;
        uint32_t gsec = min(min(min(c0, c1), min(c2, c3)),
                            min(min(c4, c5), min(c6, c7)));

        int j = (int)(gbest & 1023u);
        if (tid == 0) total += sqrtf(__uint_as_float(gbest & 0xFFFFFC00u));

        // ---- row j: speculation hit -> already in registers ----
        uint4 R;
        if (j == spec_idx) {
            R = SPEC;
        } else {
            R = ((const uint4*)(Db + ((size_t)j << 10)))[tid];
        }
        // prefetch runner-up's row for next iteration
        int sj = (int)(gsec & 1023u);
        SPEC = ((const uint4*)(Db + ((size_t)sj << 10)))[tid];
        spec_idx = (gsec == UMAX) ? -1 : sj;

        // ---- sticky min-update with fused visited-marking ----
        m.x = upd(m.x, R.x, p0 + 0, j);
        m.y = upd(m.y, R.y, p0 + 1, j);
        m.z = upd(m.z, R.z, p0 + 2, j);
        m.w = upd(m.w, R.w, p0 + 3, j);
        // next iteration writes the other parity buffer -> no WAR hazard
    }
    if (tid == 0) g_partial[b] = total;
}

// ---------------------------------------------------------------------------
// Kernel 4: final scalar.
// ---------------------------------------------------------------------------
__global__ void final_kernel(float* __restrict__ out) {
    const int t = threadIdx.x;           // 128 threads
    const int lane = t & 31, wid = t >> 5;
    __shared__ float s[4];
    float v = g_partial[t];
    #pragma unroll
    for (int o = 16; o; o >>= 1) v += __shfl_down_sync(0xffffffffu, v, o);
    if (lane == 0) s[wid] = v;
    __syncthreads();
    if (t == 0) out[0] = (s[0] + s[1] + s[2] + s[3]) / (1023.f * (float)BATCH * 2.f);
}

// ---------------------------------------------------------------------------
extern "C" void kernel_launch(void* const* d_in, const int* in_sizes, int n_in,
                              void* d_out, int out_size) {
    (void)in_sizes; (void)n_in; (void)out_size;
    const float* X = (const float*)d_in[0];
    float* out = (float*)d_out;

    prep_kernel<<<16384, 256>>>(X);            // fused norms + bf16 convert
    dist_kernel<<<dim3(8, 8, BATCH), 256>>>();
    prim_kernel<<<BATCH, 256>>>();
    final_kernel<<<1, 128>>>(out);
}